// round 13
// baseline (speedup 1.0000x reference)
#include <cuda_runtime.h>
#include <cuda_bf16.h>
#include <cstdint>

// ConvPooler — per-token dot(h[b,s,:], w) + bias scattered into
// out[b, gene_pos[b,s]] over a [B, 60000] zeroed buffer; pad id 60000 dropped.
// B=32, S=2048, D=512, FULL_SEQ_LEN=60000. gene_pos is int32.
//
// Single fused persistent kernel (296 blocks = 2 CTAs/SM, co-residency
// guaranteed by __launch_bounds__(256,2)):
//   1. zero-store out[] (bounded burst at kernel start)
//   2. arrive at grid barrier — but do NOT wait
//   3. run the pipelined conv immediately (pure read stream)
//   4. each warp's scatter lanes lazily wait for the barrier release before
//      their FIRST store to out — barrier + zero-drain hidden under the
//      first conv iteration's load latency.

#define B_DIM 32
#define S_DIM 2048
#define D_DIM 512
#define FULL_SEQ 60000
#define NTOK (B_DIM * S_DIM)          // 65536 tokens
#define NPAIRS (NTOK / 2)             // 32768 token pairs
#define GRID_BLOCKS 296               // 2 per SM on 148 SMs — all co-resident
#define BLOCK_THREADS 256

// Replay-safe barrier: g_release is monotonic across graph replays; g_arrive
// is reset by the last arriver. Every thread snapshots release BEFORE its
// block arrives (ordered by __syncthreads), so a bump can never be missed.
__device__ unsigned int g_arrive  = 0;
__device__ volatile unsigned int g_release = 0;

__global__ __launch_bounds__(BLOCK_THREADS, 2)   // reg cap 128 -> 2 CTAs/SM
void convpooler_fused_kernel(const float4* __restrict__ h,     // [B*S, D/4]
                             const int* __restrict__ gene_pos, // [B*S]
                             const float4* __restrict__ w,     // [D/4]
                             const float* __restrict__ bias,   // [1]
                             float* __restrict__ out,          // [B, FULL_SEQ]
                             int n4) {                         // out_size/4
    const int tid  = threadIdx.x;
    const int lane = tid & 31;
    const int gtid = blockIdx.x * blockDim.x + tid;
    const int nthr = gridDim.x * blockDim.x;     // 75776

    // Snapshot release BEFORE this block arrives (replay safety).
    const unsigned int snap = g_release;

    // ---- Step 1: zero-store burst (~6.3 STG.128 per thread) ----
    float4* out4 = (float4*)out;
    const float4 z = make_float4(0.f, 0.f, 0.f, 0.f);
    for (int i = gtid; i < n4; i += nthr) out4[i] = z;

    // ---- Step 2: arrive (no wait) ----
    __threadfence();            // make this thread's zero-stores visible
    __syncthreads();            // all snaps read + all stores fenced first
    if (tid == 0) {
        unsigned int old = atomicAdd(&g_arrive, 1u);
        if (old == (unsigned int)(gridDim.x - 1)) {
            g_arrive = 0;                              // reset for next replay
            __threadfence();
            atomicAdd((unsigned int*)&g_release, 1u);  // release
        }
    }
    // Fall straight into conv — no block-wide wait.

    // ---- Step 3: conv, software-pipelined, direct scatter ----
    const float4 w0 = w[lane];
    const float4 w1 = w[lane + 32];
    const float4 w2 = w[lane + 64];
    const float4 w3 = w[lane + 96];
    const float bb = bias[0];

    const int gwarp  = gtid >> 5;
    const int nwarps = nthr >> 5;                // 2368

    bool released = false;                       // lazy barrier state (per thread)

    int p = gwarp;
    if (p >= NPAIRS) return;

    const float4* base = h + (size_t)p * (2 * D_DIM / 4);
    float4 a0 = base[lane      ], a1 = base[lane +  32];
    float4 a2 = base[lane +  64], a3 = base[lane +  96];
    float4 c0 = base[lane + 128], c1 = base[lane + 160];
    float4 c2 = base[lane + 192], c3 = base[lane + 224];

    for (;;) {
        const int pn = p + nwarps;
        const bool more = (pn < NPAIRS);

        // Prefetch next pair — in flight during the FMA/shfl chain.
        float4 na0, na1, na2, na3, nc0, nc1, nc2, nc3;
        if (more) {
            const float4* nb = h + (size_t)pn * (2 * D_DIM / 4);
            na0 = nb[lane      ]; na1 = nb[lane +  32];
            na2 = nb[lane +  64]; na3 = nb[lane +  96];
            nc0 = nb[lane + 128]; nc1 = nb[lane + 160];
            nc2 = nb[lane + 192]; nc3 = nb[lane + 224];
        }

        float acc0, acc1;
        acc0 = a0.x * w0.x;
        acc0 = fmaf(a0.y, w0.y, acc0); acc0 = fmaf(a0.z, w0.z, acc0); acc0 = fmaf(a0.w, w0.w, acc0);
        acc0 = fmaf(a1.x, w1.x, acc0); acc0 = fmaf(a1.y, w1.y, acc0); acc0 = fmaf(a1.z, w1.z, acc0); acc0 = fmaf(a1.w, w1.w, acc0);
        acc0 = fmaf(a2.x, w2.x, acc0); acc0 = fmaf(a2.y, w2.y, acc0); acc0 = fmaf(a2.z, w2.z, acc0); acc0 = fmaf(a2.w, w2.w, acc0);
        acc0 = fmaf(a3.x, w3.x, acc0); acc0 = fmaf(a3.y, w3.y, acc0); acc0 = fmaf(a3.z, w3.z, acc0); acc0 = fmaf(a3.w, w3.w, acc0);
        acc1 = c0.x * w0.x;
        acc1 = fmaf(c0.y, w0.y, acc1); acc1 = fmaf(c0.z, w0.z, acc1); acc1 = fmaf(c0.w, w0.w, acc1);
        acc1 = fmaf(c1.x, w1.x, acc1); acc1 = fmaf(c1.y, w1.y, acc1); acc1 = fmaf(c1.z, w1.z, acc1); acc1 = fmaf(c1.w, w1.w, acc1);
        acc1 = fmaf(c2.x, w2.x, acc1); acc1 = fmaf(c2.y, w2.y, acc1); acc1 = fmaf(c2.z, w2.z, acc1); acc1 = fmaf(c2.w, w2.w, acc1);
        acc1 = fmaf(c3.x, w3.x, acc1); acc1 = fmaf(c3.y, w3.y, acc1); acc1 = fmaf(c3.z, w3.z, acc1); acc1 = fmaf(c3.w, w3.w, acc1);

#pragma unroll
        for (int off = 16; off > 0; off >>= 1) {
            acc0 += __shfl_xor_sync(0xFFFFFFFFu, acc0, off);
            acc1 += __shfl_xor_sync(0xFFFFFFFFu, acc1, off);
        }

        if (lane < 2) {
            // Lazy barrier wait: only before this thread's FIRST scatter.
            if (!released) {
                while (g_release == snap) { }
                __threadfence();           // acquire: zeros of all blocks visible
                released = true;
            }
            const int tok = p * 2 + lane;
            const int gp  = gene_pos[tok];
            if (gp >= 0 && gp < FULL_SEQ) {
                const int row = tok >> 11;   // tok / S_DIM
                out[(size_t)row * FULL_SEQ + (size_t)gp] =
                    (lane == 0 ? acc0 : acc1) + bb;
            }
        }

        if (!more) break;
        p = pn;
        a0 = na0; a1 = na1; a2 = na2; a3 = na3;
        c0 = nc0; c1 = nc1; c2 = nc2; c3 = nc3;
    }
}

// ---------------------------------------------------------------------------
// Launch — map inputs by element count (robust to metadata ordering):
// h=33554432, gene_pos=65536, w=512, b=1.
// ---------------------------------------------------------------------------
extern "C" void kernel_launch(void* const* d_in, const int* in_sizes, int n_in,
                              void* d_out, int out_size) {
    const void* h_p = nullptr;
    const void* gp_p = nullptr;
    const void* w_p = nullptr;
    const void* b_p = nullptr;
    for (int i = 0; i < n_in; ++i) {
        switch (in_sizes[i]) {
            case B_DIM * S_DIM * D_DIM: h_p  = d_in[i]; break;  // 33,554,432
            case B_DIM * S_DIM:         gp_p = d_in[i]; break;  // 65,536
            case D_DIM:                 w_p  = d_in[i]; break;  // 512
            case 1:                     b_p  = d_in[i]; break;
            default: break;
        }
    }

    convpooler_fused_kernel<<<GRID_BLOCKS, BLOCK_THREADS>>>(
        (const float4*)h_p, (const int*)gp_p, (const float4*)w_p,
        (const float*)b_p, (float*)d_out, out_size / 4);
}

// round 14
// speedup vs baseline: 1.4929x; 1.4929x over previous
#include <cuda_runtime.h>
#include <cuda_bf16.h>
#include <cstdint>

// ConvPooler — per-token dot(h[b,s,:], w) + bias scattered into
// out[b, gene_pos[b,s]] over a [B, 60000] zeroed buffer; pad id 60000 dropped.
// B=32, S=2048, D=512, FULL_SEQ_LEN=60000. gene_pos is int32.
//
// Fused persistent kernel (296 blocks = 2 CTAs/SM, co-residency guaranteed
// by __launch_bounds__(256,2)):
//   1. issue FIRST conv pair loads (8x LDG.128/lane, in flight)
//   2. zero-store burst of out[] — drains while the loads are in flight
//   3. R11 blocking grid barrier (replay-safe)
//   4. pipelined conv loop (identical to R11 — no volatile/spin inside)
// The zero drain + barrier are hidden under the prologue load latency.

#define B_DIM 32
#define S_DIM 2048
#define D_DIM 512
#define FULL_SEQ 60000
#define NPAIRS (B_DIM * S_DIM / 2)   // 32768 token pairs
#define GRID_BLOCKS 296               // 2 per SM on 148 SMs — all co-resident
#define BLOCK_THREADS 256

// Replay-safe barrier: g_release monotonic across graph replays; g_arrive
// reset by the last arriver. Snapshot-before-arrive -> no missed release.
__device__ unsigned int g_arrive  = 0;
__device__ volatile unsigned int g_release = 0;

__global__ __launch_bounds__(BLOCK_THREADS, 2)   // reg cap 128 -> 2 CTAs/SM
void convpooler_fused_kernel(const float4* __restrict__ h,     // [B*S, D/4]
                             const int* __restrict__ gene_pos, // [B*S]
                             const float4* __restrict__ w,     // [D/4]
                             const float* __restrict__ bias,   // [1]
                             float* __restrict__ out,          // [B, FULL_SEQ]
                             int n4) {                         // out_size/4
    const int tid  = threadIdx.x;
    const int lane = tid & 31;
    const int gtid = blockIdx.x * blockDim.x + tid;
    const int nthr = gridDim.x * blockDim.x;     // 75776

    const int gwarp  = gtid >> 5;
    const int nwarps = nthr >> 5;                // 2368

    // ---- Step 1: issue first-pair loads + w loads (all in flight) ----
    int p = gwarp;                               // gwarp < NPAIRS always (2368 < 32768)
    const float4* base = h + (size_t)p * (2 * D_DIM / 4);
    float4 a0 = base[lane      ], a1 = base[lane +  32];
    float4 a2 = base[lane +  64], a3 = base[lane +  96];
    float4 c0 = base[lane + 128], c1 = base[lane + 160];
    float4 c2 = base[lane + 192], c3 = base[lane + 224];
    const float4 w0 = w[lane];
    const float4 w1 = w[lane + 32];
    const float4 w2 = w[lane + 64];
    const float4 w3 = w[lane + 96];
    const float bb = bias[0];

    // ---- Step 2: zero-store burst (~6.3 STG.128/thread) ----
    // Drains to HBM while the step-1 loads are still in flight.
    {
        float4* out4 = (float4*)out;
        const float4 z = make_float4(0.f, 0.f, 0.f, 0.f);
        for (int i = gtid; i < n4; i += nthr) out4[i] = z;
    }

    // ---- Step 3: blocking grid barrier (R11-proven) ----
    __syncthreads();
    if (tid == 0) {
        unsigned int snap = g_release;          // snapshot BEFORE arriving
        __threadfence();                        // zero-stores visible first
        unsigned int old = atomicAdd(&g_arrive, 1u);
        if (old == (unsigned int)(gridDim.x - 1)) {
            g_arrive = 0;                       // reset for next replay
            __threadfence();
            atomicAdd((unsigned int*)&g_release, 1u);  // release
        } else {
            while (g_release == snap) { }       // one-shot poll, outside loop
        }
        __threadfence();                        // acquire
    }
    __syncthreads();

    // ---- Step 4: pipelined conv loop (identical to R11) ----
    for (;;) {
        const int pn = p + nwarps;
        const bool more = (pn < NPAIRS);

        // Prefetch next pair — in flight during the FMA/shfl chain.
        float4 na0, na1, na2, na3, nc0, nc1, nc2, nc3;
        if (more) {
            const float4* nb = h + (size_t)pn * (2 * D_DIM / 4);
            na0 = nb[lane      ]; na1 = nb[lane +  32];
            na2 = nb[lane +  64]; na3 = nb[lane +  96];
            nc0 = nb[lane + 128]; nc1 = nb[lane + 160];
            nc2 = nb[lane + 192]; nc3 = nb[lane + 224];
        }

        float acc0, acc1;
        acc0 = a0.x * w0.x;
        acc0 = fmaf(a0.y, w0.y, acc0); acc0 = fmaf(a0.z, w0.z, acc0); acc0 = fmaf(a0.w, w0.w, acc0);
        acc0 = fmaf(a1.x, w1.x, acc0); acc0 = fmaf(a1.y, w1.y, acc0); acc0 = fmaf(a1.z, w1.z, acc0); acc0 = fmaf(a1.w, w1.w, acc0);
        acc0 = fmaf(a2.x, w2.x, acc0); acc0 = fmaf(a2.y, w2.y, acc0); acc0 = fmaf(a2.z, w2.z, acc0); acc0 = fmaf(a2.w, w2.w, acc0);
        acc0 = fmaf(a3.x, w3.x, acc0); acc0 = fmaf(a3.y, w3.y, acc0); acc0 = fmaf(a3.z, w3.z, acc0); acc0 = fmaf(a3.w, w3.w, acc0);
        acc1 = c0.x * w0.x;
        acc1 = fmaf(c0.y, w0.y, acc1); acc1 = fmaf(c0.z, w0.z, acc1); acc1 = fmaf(c0.w, w0.w, acc1);
        acc1 = fmaf(c1.x, w1.x, acc1); acc1 = fmaf(c1.y, w1.y, acc1); acc1 = fmaf(c1.z, w1.z, acc1); acc1 = fmaf(c1.w, w1.w, acc1);
        acc1 = fmaf(c2.x, w2.x, acc1); acc1 = fmaf(c2.y, w2.y, acc1); acc1 = fmaf(c2.z, w2.z, acc1); acc1 = fmaf(c2.w, w2.w, acc1);
        acc1 = fmaf(c3.x, w3.x, acc1); acc1 = fmaf(c3.y, w3.y, acc1); acc1 = fmaf(c3.z, w3.z, acc1); acc1 = fmaf(c3.w, w3.w, acc1);

#pragma unroll
        for (int off = 16; off > 0; off >>= 1) {
            acc0 += __shfl_xor_sync(0xFFFFFFFFu, acc0, off);
            acc1 += __shfl_xor_sync(0xFFFFFFFFu, acc1, off);
        }

        if (lane < 2) {
            const int tok = p * 2 + lane;
            const int gp  = gene_pos[tok];
            if (gp >= 0 && gp < FULL_SEQ) {
                const int row = tok >> 11;   // tok / S_DIM
                out[(size_t)row * FULL_SEQ + (size_t)gp] =
                    (lane == 0 ? acc0 : acc1) + bb;
            }
        }

        if (!more) break;
        p = pn;
        a0 = na0; a1 = na1; a2 = na2; a3 = na3;
        c0 = nc0; c1 = nc1; c2 = nc2; c3 = nc3;
    }
}

// ---------------------------------------------------------------------------
// Launch — map inputs by element count (robust to metadata ordering):
// h=33554432, gene_pos=65536, w=512, b=1.
// ---------------------------------------------------------------------------
extern "C" void kernel_launch(void* const* d_in, const int* in_sizes, int n_in,
                              void* d_out, int out_size) {
    const void* h_p = nullptr;
    const void* gp_p = nullptr;
    const void* w_p = nullptr;
    const void* b_p = nullptr;
    for (int i = 0; i < n_in; ++i) {
        switch (in_sizes[i]) {
            case B_DIM * S_DIM * D_DIM: h_p  = d_in[i]; break;  // 33,554,432
            case B_DIM * S_DIM:         gp_p = d_in[i]; break;  // 65,536
            case D_DIM:                 w_p  = d_in[i]; break;  // 512
            case 1:                     b_p  = d_in[i]; break;
            default: break;
        }
    }

    convpooler_fused_kernel<<<GRID_BLOCKS, BLOCK_THREADS>>>(
        (const float4*)h_p, (const int*)gp_p, (const float4*)w_p,
        (const float*)b_p, (float*)d_out, out_size / 4);
}